// round 4
// baseline (speedup 1.0000x reference)
#include <cuda_runtime.h>
#include <cuda_fp16.h>

// DAGNN: deg-norm, 10x SpMM (CSR gather, fp16 hop slices), deferred fused pooling.
// N=100000, D=64, E=1600000, K=10.

#define MAX_N 100000
#define MAX_E 1600000
#define D 64
#define KHOPS 10
#define FULLMASK 0xffffffffu

// ---------------- device scratch (static: allocation-free rule) ----------------
// q_t = norm*h_t slices, t=0..K  (q_0 = norm*features)
__device__ __align__(256) __half g_q[(KHOPS + 1) * (size_t)MAX_N * D];
__device__ float g_norm2[MAX_N];     // 1/max(deg,1)        (= norm^2)
__device__ float g_invn[MAX_N];      // sqrt(max(deg,1))    (= 1/norm)
__device__ int   g_deg[MAX_N];
__device__ int   g_cursor[MAX_N];
__device__ int   g_rowptr[MAX_N + 1];
__device__ int   g_csr_src[MAX_E];
__device__ int   g_idx64;            // 1 if src/dst are int64, 0 if int32

// ---------------- k1: init + dtype probe ----------------
__global__ void init_kernel(const void* __restrict__ dst, int n) {
    if (blockIdx.x == 0) {
        // int64 values < 2^31 have zero odd 32-bit words; int32 ids are random.
        const unsigned* w = (const unsigned*)dst;
        int ok = (w[2 * threadIdx.x + 1] == 0u) ? 1 : 0;
        int all = __syncthreads_and(ok);
        if (threadIdx.x == 0) g_idx64 = all;
    }
    for (int i = blockIdx.x * blockDim.x + threadIdx.x; i < n;
         i += gridDim.x * blockDim.x) {
        g_deg[i] = 0;
        g_cursor[i] = 0;
    }
}

__device__ __forceinline__ int read_idx(const void* p, int i, int is64) {
    if (is64) return (int)((const long long*)p)[i];
    return ((const int*)p)[i];
}

// ---------------- k2: degree count ----------------
__global__ void deg_kernel(const void* __restrict__ dst, int e) {
    int is64 = g_idx64;
    for (int i = blockIdx.x * blockDim.x + threadIdx.x; i < e;
         i += gridDim.x * blockDim.x) {
        atomicAdd(&g_deg[read_idx(dst, i, is64)], 1);
    }
}

// ---------------- k3: norm terms + exclusive scan (one block) ----------------
__global__ void normscan_kernel(int n) {
    __shared__ int part[1024];
    int t = threadIdx.x;
    int chunk = (n + 1023) / 1024;
    int beg = t * chunk;
    int end = beg + chunk;
    if (beg > n) beg = n;
    if (end > n) end = n;
    int s = 0;
    for (int i = beg; i < end; ++i) {
        int d = g_deg[i];
        float df = fmaxf((float)d, 1.0f);
        g_norm2[i] = 1.0f / df;
        g_invn[i] = sqrtf(df);
        s += d;
    }
    part[t] = s;
    __syncthreads();
    if (t == 0) {
        int acc = 0;
        for (int i = 0; i < 1024; ++i) { int v = part[i]; part[i] = acc; acc += v; }
    }
    __syncthreads();
    int acc = part[t];
    for (int i = beg; i < end; ++i) { g_rowptr[i] = acc; acc += g_deg[i]; }
    if (t == 1023) g_rowptr[n] = acc;
}

// ---------------- k4: CSR fill ----------------
__global__ void fill_kernel(const void* __restrict__ src,
                            const void* __restrict__ dst, int e) {
    int is64 = g_idx64;
    for (int i = blockIdx.x * blockDim.x + threadIdx.x; i < e;
         i += gridDim.x * blockDim.x) {
        int d = read_idx(dst, i, is64);
        int p = atomicAdd(&g_cursor[d], 1);
        g_csr_src[g_rowptr[d] + p] = read_idx(src, i, is64);
    }
}

// ---------------- k5: q_0 = fp16(norm * f) ----------------
__global__ void prep_kernel(const float* __restrict__ feat,
                            __half2* __restrict__ q0, int n) {
    int idx = blockIdx.x * blockDim.x + threadIdx.x;     // half2 index
    int total = n * (D / 2);
    if (idx >= total) return;
    int node = idx >> 5;                                  // D/2 = 32
    float nm = rsqrtf(fmaxf((float)g_deg[node], 1.0f));
    float2 f = ((const float2*)feat)[idx];
    float2 g; g.x = nm * f.x; g.y = nm * f.y;
    q0[idx] = __float22half2_rn(g);
}

// ---------------- hop: q_t[i] = norm2[i] * sum_{s in N(i)} q_{t-1}[s] ----------
__global__ void hop_kernel(const __half2* __restrict__ qin,
                           __half2* __restrict__ qout, int n) {
    int warp = (blockIdx.x * blockDim.x + threadIdx.x) >> 5;
    int lane = threadIdx.x & 31;
    if (warp >= n) return;
    int beg = g_rowptr[warp];
    int deg = g_rowptr[warp + 1] - beg;
    float a0 = 0.0f, a1 = 0.0f;
    for (int base = 0; base < deg; base += 32) {
        int m = deg - base; if (m > 32) m = 32;
        int myidx = (lane < m) ? g_csr_src[beg + base + lane] : 0;
        #pragma unroll 8
        for (int j = 0; j < m; ++j) {
            int sn = __shfl_sync(FULLMASK, myidx, j);
            float2 v = __half22float2(qin[sn * 32 + lane]);  // 128B coalesced
            a0 += v.x; a1 += v.y;
        }
    }
    float n2 = g_norm2[warp];
    float2 g; g.x = n2 * a0; g.y = n2 * a1;
    qout[warp * 32 + lane] = __float22half2_rn(g);
}

// ---------------- pool: out = sig(f.s)f + sum_t sig(h_t.s) h_t ----------------
__global__ void pool_kernel(const float* __restrict__ feat,
                            const float* __restrict__ s,
                            float* __restrict__ out, int n) {
    int warp = (blockIdx.x * blockDim.x + threadIdx.x) >> 5;
    int lane = threadIdx.x & 31;
    if (warp >= n) return;
    int base = warp * 32 + lane;                 // half2 units
    float2 sv = ((const float2*)s)[lane];
    float inv = g_invn[warp];

    // t = 0 term (exact fp32 features)
    float2 f = ((const float2*)feat)[base];
    float dot = f.x * sv.x + f.y * sv.y;
    #pragma unroll
    for (int off = 16; off; off >>= 1) dot += __shfl_xor_sync(FULLMASK, dot, off);
    float sig = 1.0f / (1.0f + __expf(-dot));
    float a0 = sig * f.x, a1 = sig * f.y;

    const __half2* q = (const __half2*)g_q;
    #pragma unroll
    for (int t = 1; t <= KHOPS; ++t) {
        float2 h = __half22float2(q[(size_t)t * MAX_N * 32 + base]);
        h.x *= inv; h.y *= inv;
        float d2 = h.x * sv.x + h.y * sv.y;
        #pragma unroll
        for (int off = 16; off; off >>= 1) d2 += __shfl_xor_sync(FULLMASK, d2, off);
        float sg = 1.0f / (1.0f + __expf(-d2));
        a0 += sg * h.x; a1 += sg * h.y;
    }
    float2 o; o.x = a0; o.y = a1;
    ((float2*)out)[base] = o;
}

// ---------------- launch ----------------
extern "C" void kernel_launch(void* const* d_in, const int* in_sizes, int n_in,
                              void* d_out, int out_size) {
    const float* feat = (const float*)d_in[0];
    const float* s    = (const float*)d_in[1];
    const void*  src  = d_in[2];
    const void*  dst  = d_in[3];
    float* out = (float*)d_out;

    int n = in_sizes[0] / D;
    int e = in_sizes[2];

    __half* dq;
    cudaGetSymbolAddress((void**)&dq, g_q);
    __half2* q = (__half2*)dq;

    const int T = 256;
    int blkN = (n + T - 1) / T;
    int blkE = (e + T - 1) / T; if (blkE > 2048) blkE = 2048;
    int blkH = (n * (D / 2) + T - 1) / T;              // elementwise half2
    int blkW = (int)(((size_t)n * 32 + T - 1) / T);    // one warp per node

    init_kernel<<<blkN, T>>>(dst, n);                  // launch 1
    deg_kernel<<<blkE, T>>>(dst, e);                   // launch 2
    normscan_kernel<<<1, 1024>>>(n);                   // launch 3
    fill_kernel<<<blkE, T>>>(src, dst, e);             // launch 4
    prep_kernel<<<blkH, T>>>(feat, q, n);              // launch 5

    for (int t = 1; t <= KHOPS; ++t) {                 // launches 6..15
        hop_kernel<<<blkW, T>>>(q + (size_t)(t - 1) * MAX_N * 32,
                                q + (size_t)t * MAX_N * 32, n);
    }
    pool_kernel<<<blkW, T>>>(feat, s, out, n);         // launch 16
    (void)n_in; (void)out_size;
}

// round 5
// speedup vs baseline: 1.5507x; 1.5507x over previous
#include <cuda_runtime.h>
#include <cuda_fp16.h>

// DAGNN: deg-norm, 10x SpMM (CSR gather, fp16 hop slices), deferred fused pooling.
// N=100000, D=64, E=1600000, K=10.

#define MAX_N 100000
#define MAX_E 1600000
#define D 64
#define KHOPS 10
#define FULLMASK 0xffffffffu

// ---------------- device scratch (static: allocation-free rule) ----------------
// q_t = norm*h_t slices, t=0..K  (q_0 = norm*features)
__device__ __align__(256) __half g_q[(KHOPS + 1) * (size_t)MAX_N * D];
__device__ float g_norm2[MAX_N];     // 1/max(deg,1)        (= norm^2)
__device__ float g_invn[MAX_N];      // sqrt(max(deg,1))    (= 1/norm)
__device__ int   g_deg[MAX_N];
__device__ int   g_cursor[MAX_N];
__device__ int   g_rowptr[MAX_N + 1];
__device__ int   g_csr_src[MAX_E];
__device__ int   g_idx64;            // 1 if src/dst are int64, 0 if int32

// ---------------- k1: init + dtype probe ----------------
__global__ void init_kernel(const void* __restrict__ dst, int n) {
    if (blockIdx.x == 0) {
        // int64 values < 2^31 have zero odd 32-bit words; int32 ids are random.
        const unsigned* w = (const unsigned*)dst;
        int ok = (w[2 * threadIdx.x + 1] == 0u) ? 1 : 0;
        int all = __syncthreads_and(ok);
        if (threadIdx.x == 0) g_idx64 = all;
    }
    for (int i = blockIdx.x * blockDim.x + threadIdx.x; i < n;
         i += gridDim.x * blockDim.x) {
        g_deg[i] = 0;
        g_cursor[i] = 0;
    }
}

__device__ __forceinline__ int read_idx(const void* p, int i, int is64) {
    if (is64) return (int)((const long long*)p)[i];
    return ((const int*)p)[i];
}

// ---------------- k2: degree count ----------------
__global__ void deg_kernel(const void* __restrict__ dst, int e) {
    int is64 = g_idx64;
    for (int i = blockIdx.x * blockDim.x + threadIdx.x; i < e;
         i += gridDim.x * blockDim.x) {
        atomicAdd(&g_deg[read_idx(dst, i, is64)], 1);
    }
}

// ---------------- k3: norm terms + exclusive scan (one block) ----------------
__global__ void normscan_kernel(int n) {
    __shared__ int part[1024];
    int t = threadIdx.x;
    int chunk = (n + 1023) / 1024;
    int beg = t * chunk;
    int end = beg + chunk;
    if (beg > n) beg = n;
    if (end > n) end = n;
    int s = 0;
    for (int i = beg; i < end; ++i) {
        int d = g_deg[i];
        float df = fmaxf((float)d, 1.0f);
        g_norm2[i] = 1.0f / df;
        g_invn[i] = sqrtf(df);
        s += d;
    }
    part[t] = s;
    __syncthreads();
    if (t == 0) {
        int acc = 0;
        for (int i = 0; i < 1024; ++i) { int v = part[i]; part[i] = acc; acc += v; }
    }
    __syncthreads();
    int acc = part[t];
    for (int i = beg; i < end; ++i) { g_rowptr[i] = acc; acc += g_deg[i]; }
    if (t == 1023) g_rowptr[n] = acc;
}

// ---------------- k4: CSR fill ----------------
__global__ void fill_kernel(const void* __restrict__ src,
                            const void* __restrict__ dst, int e) {
    int is64 = g_idx64;
    for (int i = blockIdx.x * blockDim.x + threadIdx.x; i < e;
         i += gridDim.x * blockDim.x) {
        int d = read_idx(dst, i, is64);
        int p = atomicAdd(&g_cursor[d], 1);
        g_csr_src[g_rowptr[d] + p] = read_idx(src, i, is64);
    }
}

// ---------------- k5: q_0 = fp16(norm * f) ----------------
__global__ void prep_kernel(const float* __restrict__ feat,
                            __half2* __restrict__ q0, int n) {
    int idx = blockIdx.x * blockDim.x + threadIdx.x;     // half2 index
    int total = n * (D / 2);
    if (idx >= total) return;
    int node = idx >> 5;                                  // D/2 = 32
    float nm = rsqrtf(fmaxf((float)g_deg[node], 1.0f));
    float2 f = ((const float2*)feat)[idx];
    float2 g; g.x = nm * f.x; g.y = nm * f.y;
    q0[idx] = __float22half2_rn(g);
}

// ---------------- hop: q_t[i] = norm2[i] * sum_{s in N(i)} q_{t-1}[s] ----------
// One warp per node; uniform index loads, front-batched gathers (high MLP).
__global__ void hop_kernel(const __half2* __restrict__ qin,
                           __half2* __restrict__ qout, int n) {
    int warp = (blockIdx.x * blockDim.x + threadIdx.x) >> 5;
    int lane = threadIdx.x & 31;
    if (warp >= n) return;
    int beg = g_rowptr[warp];
    int end = g_rowptr[warp + 1];
    float a0 = 0.0f, a1 = 0.0f;
    #pragma unroll 4
    for (int j = beg; j < end; ++j) {
        int sn = g_csr_src[j];                           // uniform (L1-hit)
        float2 v = __half22float2(qin[sn * 32 + lane]);  // 128B coalesced
        a0 += v.x; a1 += v.y;
    }
    float n2 = g_norm2[warp];
    float2 g; g.x = n2 * a0; g.y = n2 * a1;
    qout[warp * 32 + lane] = __float22half2_rn(g);
}

// ---------------- pool: out = sig(f.s)f + sum_t sig(h_t.s) h_t ----------------
__global__ void pool_kernel(const float* __restrict__ feat,
                            const float* __restrict__ s,
                            float* __restrict__ out, int n) {
    int warp = (blockIdx.x * blockDim.x + threadIdx.x) >> 5;
    int lane = threadIdx.x & 31;
    if (warp >= n) return;
    int base = warp * 32 + lane;                 // half2 units
    float2 sv = ((const float2*)s)[lane];
    float inv = g_invn[warp];

    // t = 0 term (exact fp32 features)
    float2 f = ((const float2*)feat)[base];
    float dot = f.x * sv.x + f.y * sv.y;
    #pragma unroll
    for (int off = 16; off; off >>= 1) dot += __shfl_xor_sync(FULLMASK, dot, off);
    float sig = 1.0f / (1.0f + __expf(-dot));
    float a0 = sig * f.x, a1 = sig * f.y;

    const __half2* q = (const __half2*)g_q;
    #pragma unroll
    for (int t = 1; t <= KHOPS; ++t) {
        float2 h = __half22float2(q[(size_t)t * MAX_N * 32 + base]);
        h.x *= inv; h.y *= inv;
        float d2 = h.x * sv.x + h.y * sv.y;
        #pragma unroll
        for (int off = 16; off; off >>= 1) d2 += __shfl_xor_sync(FULLMASK, d2, off);
        float sg = 1.0f / (1.0f + __expf(-d2));
        a0 += sg * h.x; a1 += sg * h.y;
    }
    float2 o; o.x = a0; o.y = a1;
    ((float2*)out)[base] = o;
}

// ---------------- launch ----------------
extern "C" void kernel_launch(void* const* d_in, const int* in_sizes, int n_in,
                              void* d_out, int out_size) {
    const float* feat = (const float*)d_in[0];
    const float* s    = (const float*)d_in[1];
    const void*  src  = d_in[2];
    const void*  dst  = d_in[3];
    float* out = (float*)d_out;

    int n = in_sizes[0] / D;
    int e = in_sizes[2];

    __half* dq;
    cudaGetSymbolAddress((void**)&dq, g_q);
    __half2* q = (__half2*)dq;

    const int T = 256;
    int blkN = (n + T - 1) / T;
    int blkE = (e + T - 1) / T; if (blkE > 2048) blkE = 2048;
    int blkH = (n * (D / 2) + T - 1) / T;              // elementwise half2
    int blkW = (int)(((size_t)n * 32 + T - 1) / T);    // one warp per node

    init_kernel<<<blkN, T>>>(dst, n);                  // launch 1
    deg_kernel<<<blkE, T>>>(dst, e);                   // launch 2
    normscan_kernel<<<1, 1024>>>(n);                   // launch 3
    fill_kernel<<<blkE, T>>>(src, dst, e);             // launch 4
    prep_kernel<<<blkH, T>>>(feat, q, n);              // launch 5

    for (int t = 1; t <= KHOPS; ++t) {                 // launches 6..15
        hop_kernel<<<blkW, T>>>(q + (size_t)(t - 1) * MAX_N * 32,
                                q + (size_t)t * MAX_N * 32, n);
    }
    pool_kernel<<<blkW, T>>>(feat, s, out, n);         // launch 16
    (void)n_in; (void)out_size;
}